// round 3
// baseline (speedup 1.0000x reference)
#include <cuda_runtime.h>
#include <cuda_bf16.h>

// Problem constants
#define B_   8
#define S1_  512
#define S2_  512
#define HID_ 128
#define HD_  128
#define TSPLIT 8

// ---------------- scratch (static device memory; no allocations) -------------
__device__ float g_qp  [B_ * S1_ * HID_];                 // 2 MB
__device__ float g_kp  [B_ * S2_ * HID_];                 // 2 MB
__device__ float g_pout[TSPLIT * B_ * S1_ * HD_];         // 16 MB
__device__ float g_pden[TSPLIT * B_ * S1_];               // 128 KB

// ---------------- packed f32x2 helpers (Blackwell-only PTX) ------------------
__device__ __forceinline__ unsigned long long f32x2_add(unsigned long long a,
                                                        unsigned long long b) {
    unsigned long long r;
    asm("add.rn.f32x2 %0, %1, %2;" : "=l"(r) : "l"(a), "l"(b));
    return r;
}
__device__ __forceinline__ unsigned long long f32x2_fma(unsigned long long a,
                                                        unsigned long long b,
                                                        unsigned long long c) {
    unsigned long long r;
    asm("fma.rn.f32x2 %0, %1, %2, %3;" : "=l"(r) : "l"(a), "l"(b), "l"(c));
    return r;
}
__device__ __forceinline__ unsigned long long f32x2_pack(float lo, float hi) {
    unsigned long long r;
    asm("mov.b64 %0, {%1, %2};" : "=l"(r) : "f"(lo), "f"(hi));
    return r;
}
__device__ __forceinline__ void f32x2_unpack(unsigned long long a, float& lo, float& hi) {
    asm("mov.b64 {%0, %1}, %2;" : "=f"(lo), "=f"(hi) : "l"(a));
}

// ================= Kernel 1: projections qp / kp =============================
// qp[r][h] = sum_d X[r][d] * W1[h][d]       + b1[h]   (query part)
// kp[r][h] = sum_d X[r][d] * W1[h][128+d]             (key part)
// grid (4096/64, 2), block 256.  Tile: 64 rows x 128 cols, K chunked by 32.
__global__ __launch_bounds__(256) void proj_kernel(
    const float* __restrict__ query, const float* __restrict__ key,
    const float* __restrict__ W1, const float* __restrict__ b1)
{
    __shared__ float xs[64][33];
    __shared__ float ws[32][132];   // 132*4 = 528 bytes per row, 16B multiple

    const int tid = threadIdx.x;
    const int tx = tid & 31;        // col group: cols tx*4 .. tx*4+3
    const int ty = tid >> 5;        // rows ty, ty+8, ..., ty+56
    const int R0 = blockIdx.x * 64;
    const int part = blockIdx.y;    // 0 = query->qp (+bias), 1 = key->kp
    const float* X = part ? key : query;
    float* out = part ? g_kp : g_qp;
    const int woff = part * 128;

    float4 acc[8];
    if (part == 0) {
        float4 bv = *reinterpret_cast<const float4*>(b1 + tx * 4);
        #pragma unroll
        for (int i = 0; i < 8; i++) acc[i] = bv;
    } else {
        #pragma unroll
        for (int i = 0; i < 8; i++) acc[i] = make_float4(0.f, 0.f, 0.f, 0.f);
    }

    for (int kc = 0; kc < 4; kc++) {
        __syncthreads();
        // load X tile [64][32]
        #pragma unroll
        for (int j = 0; j < 2; j++) {
            int idx = tid + j * 256;            // 0..511 float4s
            int r = idx >> 3, kk = (idx & 7) * 4;
            float4 xv = *reinterpret_cast<const float4*>(
                X + (size_t)(R0 + r) * 128 + kc * 32 + kk);
            xs[r][kk + 0] = xv.x; xs[r][kk + 1] = xv.y;
            xs[r][kk + 2] = xv.z; xs[r][kk + 3] = xv.w;
        }
        // load W tile transposed: ws[k][h] = W1[h][woff + kc*32 + k]
        #pragma unroll
        for (int j = 0; j < 4; j++) {
            int idx = tid + j * 256;            // 0..1023 float4s
            int h = idx >> 3, k4 = (idx & 7) * 4;
            float4 wv = *reinterpret_cast<const float4*>(
                W1 + (size_t)h * 256 + woff + kc * 32 + k4);
            ws[k4 + 0][h] = wv.x; ws[k4 + 1][h] = wv.y;
            ws[k4 + 2][h] = wv.z; ws[k4 + 3][h] = wv.w;
        }
        __syncthreads();

        #pragma unroll 8
        for (int k = 0; k < 32; k++) {
            float4 wv = *reinterpret_cast<const float4*>(&ws[k][tx * 4]);
            #pragma unroll
            for (int i = 0; i < 8; i++) {
                float xv = xs[ty + 8 * i][k];
                acc[i].x = fmaf(xv, wv.x, acc[i].x);
                acc[i].y = fmaf(xv, wv.y, acc[i].y);
                acc[i].z = fmaf(xv, wv.z, acc[i].z);
                acc[i].w = fmaf(xv, wv.w, acc[i].w);
            }
        }
    }
    #pragma unroll
    for (int i = 0; i < 8; i++) {
        int r = R0 + ty + 8 * i;
        *reinterpret_cast<float4*>(out + (size_t)r * 128 + tx * 4) = acc[i];
    }
}

// ================= Kernel 2: fused scoring + exp + mask + value accum ========
// grid (S1/32, TSPLIT, B), block 256 (8 warps).
// Warp handles 4 s values; lane = s_local*8 + hc; lane owns h/d chunk hc*16..+15.
__global__ __launch_bounds__(256) void attn_kernel(
    const float* __restrict__ value, const int* __restrict__ k_mask,
    const float* __restrict__ W2, const float* __restrict__ b2)
{
    // Permuted layout: float4 chunk (hc, ib) of a 128-float row lives at
    // slot ib*8 + hc  => per-t reads (ib fixed, hc = lane&7) are bank-free.
    __shared__ float kp_s[32 * 128];
    __shared__ float v_s [32 * 128];
    __shared__ float km_s[32];

    const int tid = threadIdx.x;
    const int warp = tid >> 5, lane = tid & 31;
    const int s_local = lane >> 3, hc = lane & 7;
    const int stile = blockIdx.x, tz = blockIdx.y, b = blockIdx.z;
    const int s = stile * 32 + warp * 4 + s_local;
    const int row = b * S1_ + s;

    // qp chunk for (s, hc*16..hc*16+15) as 8 packed pairs
    unsigned long long qp2[8];
    {
        const float4* qrow = reinterpret_cast<const float4*>(
            g_qp + (size_t)row * HID_ + hc * 16);
        #pragma unroll
        for (int i = 0; i < 4; i++) {
            float4 q = qrow[i];
            qp2[2 * i]     = f32x2_pack(q.x, q.y);
            qp2[2 * i + 1] = f32x2_pack(q.z, q.w);
        }
    }
    float w2r[16];
    #pragma unroll
    for (int i = 0; i < 16; i++) w2r[i] = W2[hc * 16 + i];
    const float b2s = b2[0];

    unsigned long long acc2[8];
    #pragma unroll
    for (int i = 0; i < 8; i++) acc2[i] = 0ULL;
    float den = 0.f;

    const int t0 = tz * (S2_ / TSPLIT);

    for (int chunk = 0; chunk < (S2_ / TSPLIT) / 32; chunk++) {
        const int tbase = t0 + chunk * 32;
        __syncthreads();
        // Cooperative load of kp/v chunk with the permutation folded into the
        // GLOBAL read index => STS is sequential (conflict-free).
        #pragma unroll
        for (int j = 0; j < 4; j++) {
            int idx = tid + j * 256;            // 0..1023 float4s
            int tt = idx >> 5, l = idx & 31;
            int h4 = ((l & 7) << 2) | (l >> 3); // inverse of slot permutation
            const float4* krow = reinterpret_cast<const float4*>(
                g_kp + (size_t)(b * S2_ + tbase + tt) * HID_);
            const float4* vrow = reinterpret_cast<const float4*>(
                value + (size_t)(b * S2_ + tbase + tt) * HD_);
            reinterpret_cast<float4*>(kp_s)[tt * 32 + l] = krow[h4];
            reinterpret_cast<float4*>(v_s )[tt * 32 + l] = vrow[h4];
        }
        if (tid < 32) km_s[tid] = (float)k_mask[b * S2_ + tbase + tid];
        __syncthreads();

        #pragma unroll 4
        for (int tt = 0; tt < 32; tt++) {
            const float* kprow = kp_s + tt * 128;
            float p0 = 0.f, p1 = 0.f;
            #pragma unroll
            for (int ib = 0; ib < 4; ib++) {
                ulonglong2 kv = *reinterpret_cast<const ulonglong2*>(
                    kprow + ib * 32 + hc * 4);
                unsigned long long a01 = f32x2_add(qp2[2 * ib],     kv.x);
                unsigned long long a23 = f32x2_add(qp2[2 * ib + 1], kv.y);
                float a0, a1, a2, a3;
                f32x2_unpack(a01, a0, a1);
                f32x2_unpack(a23, a2, a3);
                p0 = fmaf(fmaxf(a0, 0.f), w2r[4 * ib + 0], p0);
                p1 = fmaf(fmaxf(a1, 0.f), w2r[4 * ib + 1], p1);
                p0 = fmaf(fmaxf(a2, 0.f), w2r[4 * ib + 2], p0);
                p1 = fmaf(fmaxf(a3, 0.f), w2r[4 * ib + 3], p1);
            }
            float sc = p0 + p1;
            sc += __shfl_xor_sync(0xffffffffu, sc, 1);
            sc += __shfl_xor_sync(0xffffffffu, sc, 2);
            sc += __shfl_xor_sync(0xffffffffu, sc, 4);
            float p = __expf(sc + b2s) * km_s[tt];
            den += p;
            unsigned long long p2 = f32x2_pack(p, p);
            const float* vrow2 = v_s + tt * 128;
            #pragma unroll
            for (int m = 0; m < 4; m++) {
                ulonglong2 vv = *reinterpret_cast<const ulonglong2*>(
                    vrow2 + m * 32 + hc * 4);
                acc2[2 * m]     = f32x2_fma(vv.x, p2, acc2[2 * m]);
                acc2[2 * m + 1] = f32x2_fma(vv.y, p2, acc2[2 * m + 1]);
            }
        }
    }

    // write partials: lane owns d = hc*16 + m*4 .. +3 for its own s
    float* outp = g_pout + ((size_t)(tz * B_ + b) * S1_ + s) * HD_ + hc * 16;
    #pragma unroll
    for (int m = 0; m < 4; m++) {
        float x0, x1, x2, x3;
        f32x2_unpack(acc2[2 * m],     x0, x1);
        f32x2_unpack(acc2[2 * m + 1], x2, x3);
        *reinterpret_cast<float4*>(outp + m * 4) = make_float4(x0, x1, x2, x3);
    }
    if (hc == 0) g_pden[(size_t)(tz * B_ + b) * S1_ + s] = den;
}

// ================= Kernel 3: reduce partials + normalize + q_mask ============
__global__ __launch_bounds__(256) void reduce_kernel(
    const int* __restrict__ q_mask, float* __restrict__ out)
{
    int idx = blockIdx.x * 256 + threadIdx.x;   // float4 index
    if (idx >= B_ * S1_ * (HD_ / 4)) return;
    int d4 = idx & 31;
    int row = idx >> 5;                          // b*S1 + s
    float4 sum = make_float4(0.f, 0.f, 0.f, 0.f);
    float dsum = 0.f;
    #pragma unroll
    for (int k = 0; k < TSPLIT; k++) {
        float4 p = reinterpret_cast<const float4*>(g_pout)
                       [((size_t)k * B_ * S1_ + row) * 32 + d4];
        sum.x += p.x; sum.y += p.y; sum.z += p.z; sum.w += p.w;
        dsum += g_pden[(size_t)k * B_ * S1_ + row];
    }
    float qm = (float)q_mask[row];
    float scale = qm / fmaxf(dsum, 2e-15f);
    reinterpret_cast<float4*>(out)[idx] =
        make_float4(sum.x * scale, sum.y * scale, sum.z * scale, sum.w * scale);
}

// ================= launch ====================================================
extern "C" void kernel_launch(void* const* d_in, const int* in_sizes, int n_in,
                              void* d_out, int out_size)
{
    const float* query  = (const float*)d_in[0];
    const float* key    = (const float*)d_in[1];
    const float* value  = (const float*)d_in[2];
    const int*   q_mask = (const int*)  d_in[3];
    const int*   k_mask = (const int*)  d_in[4];
    const float* W1     = (const float*)d_in[5];
    const float* b1     = (const float*)d_in[6];
    const float* W2     = (const float*)d_in[7];
    const float* b2     = (const float*)d_in[8];
    float* out = (float*)d_out;

    proj_kernel  <<<dim3(64, 2), 256>>>(query, key, W1, b1);
    attn_kernel  <<<dim3(S1_ / 32, TSPLIT, B_), 256>>>(value, k_mask, W2, b2);
    reduce_kernel<<<(B_ * S1_ * (HD_ / 4) + 255) / 256, 256>>>(q_mask, out);
}